// round 6
// baseline (speedup 1.0000x reference)
#include <cuda_runtime.h>

// LEConv on GB300 (sm_103a)
// out[v] = x[v]@W_self + xs[v]@W_src - deg[v]*(x[v]@W_dst)
//          + b_self + deg[v]*(b_src - b_dst)
// where xs[v] = sum over incoming edges of x[row], deg[v] = in-degree.
//
// Pipeline (all on default stream, graph-capturable, alloc-free):
//   1. detect_kernel : sniff edge_index dtype (int64 vs int32)
//   2. zero_kernel   : clear xs / deg scratch (device globals)
//   3. scatter_kernel: edge-parallel red.global.add.v4.f32 into xs, deg++
//   4. gemm_kernel   : fused M=50000, N=256, K=768 fp32 GEMM + epilogue

#define N_NODES 50000
#define N_EDGES 800000
#define D 256

__device__ float g_xs[(size_t)N_NODES * D];   // 51.2 MB scratch
__device__ int   g_deg[N_NODES];
__device__ int   g_is64;

// ---------------------------------------------------------------------------
// Detect edge_index element width. The buffer is at least 2*E int32 words
// (= 1.6M words). If the data is int64, words [0, 1.6M) cover the first
// 800K int64 values (the "row" array); every odd word is a high half == 0
// (values in [0, 50000)). If int32, odd words are random edge indices and
// the chance all 4096 samples are zero is ~(1/50000)^4096.
// ---------------------------------------------------------------------------
__global__ void detect_kernel(const unsigned int* __restrict__ w) {
    __shared__ int any_nonzero;
    if (threadIdx.x == 0) any_nonzero = 0;
    __syncthreads();
    int found = 0;
    for (int i = threadIdx.x; i < 4096; i += 256) {
        long long ofs = 1 + (long long)i * 390;   // odd offsets, max 1,597,051 < 1.6M
        if (w[ofs] != 0u) found = 1;
    }
    if (found) any_nonzero = 1;
    __syncthreads();
    if (threadIdx.x == 0) g_is64 = (any_nonzero == 0) ? 1 : 0;
}

// ---------------------------------------------------------------------------
// Zero the scatter accumulators.
// ---------------------------------------------------------------------------
__global__ void zero_kernel() {
    long long i = (long long)blockIdx.x * blockDim.x + threadIdx.x;
    if (i < (long long)N_NODES * D / 4)
        reinterpret_cast<float4*>(g_xs)[i] = make_float4(0.f, 0.f, 0.f, 0.f);
    if (i < N_NODES) g_deg[i] = 0;
}

// ---------------------------------------------------------------------------
// Edge scatter: one work item = (edge, 16B chunk). 64 consecutive threads
// share an edge -> coalesced 1KB gather of x[row] and coalesced v4 reds
// into xs[col]. x (50MB) and xs (51MB) are both L2-resident.
// ---------------------------------------------------------------------------
__global__ void scatter_kernel(const void* __restrict__ ei,
                               const float* __restrict__ x) {
    long long idx = (long long)blockIdx.x * blockDim.x + threadIdx.x;
    if (idx >= (long long)N_EDGES * (D / 4)) return;
    const int e = (int)(idx >> 6);
    const int c = (int)(idx & 63);

    int row, col;
    if (g_is64) {
        const long long* p = (const long long*)ei;
        row = (int)p[e];
        col = (int)p[N_EDGES + e];
    } else {
        const int* p = (const int*)ei;
        row = p[e];
        col = p[N_EDGES + e];
    }

    float4 v = __ldg(reinterpret_cast<const float4*>(x + (long long)row * D) + c);
    float* dst = g_xs + (long long)col * D + c * 4;
    asm volatile("red.global.add.v4.f32 [%0], {%1,%2,%3,%4};"
                 :: "l"(dst), "f"(v.x), "f"(v.y), "f"(v.z), "f"(v.w)
                 : "memory");
    if (c == 0) atomicAdd(&g_deg[col], 1);
}

// ---------------------------------------------------------------------------
// Fused GEMM: virtual A'' = [x | xs | deg*x]  (M x 768)
//             virtual B'' = [W_self ; W_src ; -W_dst]  (768 x 256)
// out = A''@B'' + b_self + deg*(b_src - b_dst)
// Tiling: BM=128, BN=128, BK=16, 256 threads, 8x8 micro-tile per thread.
// ---------------------------------------------------------------------------
__global__ __launch_bounds__(256, 2)
void gemm_kernel(const float* __restrict__ x,
                 const float* __restrict__ Wsrc,  const float* __restrict__ bsrc,
                 const float* __restrict__ Wdst,  const float* __restrict__ bdst,
                 const float* __restrict__ Wself, const float* __restrict__ bself,
                 float* __restrict__ out) {
    __shared__ float As[16][132];   // [k][m], +4 pad
    __shared__ float Bs[16][128];   // [k][n]

    const int tid = threadIdx.x;
    const int bm  = blockIdx.x * 128;
    const int bn  = blockIdx.y * 128;
    const int tx  = tid & 15;       // 16 col-threads
    const int ty  = tid >> 4;       // 16 row-threads

    // A-loader geometry: 128 rows x 16 k = 2048 floats = 2 float4 per thread
    const int arow = tid >> 2;              // 0..63
    const int akq  = (tid & 3) << 2;        // 0,4,8,12
    const int v0 = bm + arow;
    const int v1 = v0 + 64;
    const bool v0ok = v0 < N_NODES;
    const bool v1ok = v1 < N_NODES;
    const float d0 = v0ok ? (float)g_deg[v0] : 0.f;
    const float d1 = v1ok ? (float)g_deg[v1] : 0.f;

    // B-loader geometry: 16 rows x 128 cols = 2 float4 per thread
    const int brow = tid >> 5;              // 0..7
    const int bcol = (tid & 31) << 2;

    float acc[8][8];
#pragma unroll
    for (int i = 0; i < 8; i++)
#pragma unroll
        for (int j = 0; j < 8; j++) acc[i][j] = 0.f;

    for (int t = 0; t < 48; t++) {
        const int k0 = t * 16;
        const float* Aseg;
        const float* Bseg;
        int koff;
        float s0, s1, bsign;
        if (k0 < 256)      { Aseg = x;    Bseg = Wself; koff = k0;       s0 = 1.f; s1 = 1.f; bsign =  1.f; }
        else if (k0 < 512) { Aseg = g_xs; Bseg = Wsrc;  koff = k0 - 256; s0 = 1.f; s1 = 1.f; bsign =  1.f; }
        else               { Aseg = x;    Bseg = Wdst;  koff = k0 - 512; s0 = d0;  s1 = d1;  bsign = -1.f; }

        float4 a0 = v0ok ? *reinterpret_cast<const float4*>(Aseg + (long long)v0 * D + koff + akq)
                         : make_float4(0.f, 0.f, 0.f, 0.f);
        float4 a1 = v1ok ? *reinterpret_cast<const float4*>(Aseg + (long long)v1 * D + koff + akq)
                         : make_float4(0.f, 0.f, 0.f, 0.f);

        float4 b0 = *reinterpret_cast<const float4*>(Bseg + (long long)(koff + brow) * D + bn + bcol);
        float4 b1 = *reinterpret_cast<const float4*>(Bseg + (long long)(koff + brow + 8) * D + bn + bcol);

        As[akq + 0][arow]      = a0.x * s0;
        As[akq + 1][arow]      = a0.y * s0;
        As[akq + 2][arow]      = a0.z * s0;
        As[akq + 3][arow]      = a0.w * s0;
        As[akq + 0][arow + 64] = a1.x * s1;
        As[akq + 1][arow + 64] = a1.y * s1;
        As[akq + 2][arow + 64] = a1.z * s1;
        As[akq + 3][arow + 64] = a1.w * s1;

        Bs[brow][bcol + 0]     = b0.x * bsign;
        Bs[brow][bcol + 1]     = b0.y * bsign;
        Bs[brow][bcol + 2]     = b0.z * bsign;
        Bs[brow][bcol + 3]     = b0.w * bsign;
        Bs[brow + 8][bcol + 0] = b1.x * bsign;
        Bs[brow + 8][bcol + 1] = b1.y * bsign;
        Bs[brow + 8][bcol + 2] = b1.z * bsign;
        Bs[brow + 8][bcol + 3] = b1.w * bsign;

        __syncthreads();

#pragma unroll
        for (int kk = 0; kk < 16; kk++) {
            float4 xa0 = *reinterpret_cast<const float4*>(&As[kk][ty * 8]);
            float4 xa1 = *reinterpret_cast<const float4*>(&As[kk][ty * 8 + 4]);
            float4 yb0 = *reinterpret_cast<const float4*>(&Bs[kk][tx * 8]);
            float4 yb1 = *reinterpret_cast<const float4*>(&Bs[kk][tx * 8 + 4]);
            const float a[8] = {xa0.x, xa0.y, xa0.z, xa0.w, xa1.x, xa1.y, xa1.z, xa1.w};
            const float b[8] = {yb0.x, yb0.y, yb0.z, yb0.w, yb1.x, yb1.y, yb1.z, yb1.w};
#pragma unroll
            for (int i = 0; i < 8; i++)
#pragma unroll
                for (int j = 0; j < 8; j++)
                    acc[i][j] += a[i] * b[j];
        }
        __syncthreads();
    }

    // Epilogue: + b_self + deg*(b_src - b_dst)
    const int jg = bn + tx * 8;
    float4 bs0 = *reinterpret_cast<const float4*>(bself + jg);
    float4 bs1 = *reinterpret_cast<const float4*>(bself + jg + 4);
    float4 br0 = *reinterpret_cast<const float4*>(bsrc + jg);
    float4 br1 = *reinterpret_cast<const float4*>(bsrc + jg + 4);
    float4 bd0 = *reinterpret_cast<const float4*>(bdst + jg);
    float4 bd1 = *reinterpret_cast<const float4*>(bdst + jg + 4);
    const float bse[8] = {bs0.x, bs0.y, bs0.z, bs0.w, bs1.x, bs1.y, bs1.z, bs1.w};
    const float bdf[8] = {br0.x - bd0.x, br0.y - bd0.y, br0.z - bd0.z, br0.w - bd0.w,
                          br1.x - bd1.x, br1.y - bd1.y, br1.z - bd1.z, br1.w - bd1.w};

#pragma unroll
    for (int i = 0; i < 8; i++) {
        const int v = bm + ty * 8 + i;
        if (v >= N_NODES) continue;
        const float dv = (float)g_deg[v];
        float4 o0, o1;
        o0.x = acc[i][0] + bse[0] + dv * bdf[0];
        o0.y = acc[i][1] + bse[1] + dv * bdf[1];
        o0.z = acc[i][2] + bse[2] + dv * bdf[2];
        o0.w = acc[i][3] + bse[3] + dv * bdf[3];
        o1.x = acc[i][4] + bse[4] + dv * bdf[4];
        o1.y = acc[i][5] + bse[5] + dv * bdf[5];
        o1.z = acc[i][6] + bse[6] + dv * bdf[6];
        o1.w = acc[i][7] + bse[7] + dv * bdf[7];
        *reinterpret_cast<float4*>(out + (long long)v * D + jg)     = o0;
        *reinterpret_cast<float4*>(out + (long long)v * D + jg + 4) = o1;
    }
}

// ---------------------------------------------------------------------------
// Inputs (metadata order): x, edge_index, W_src, b_src, W_dst, b_dst,
//                          W_self, b_self.  Output: float32 [50000, 256].
// ---------------------------------------------------------------------------
extern "C" void kernel_launch(void* const* d_in, const int* in_sizes, int n_in,
                              void* d_out, int out_size) {
    const float* x     = (const float*)d_in[0];
    const void*  ei    = d_in[1];
    const float* Wsrc  = (const float*)d_in[2];
    const float* bsrc  = (const float*)d_in[3];
    const float* Wdst  = (const float*)d_in[4];
    const float* bdst  = (const float*)d_in[5];
    const float* Wself = (const float*)d_in[6];
    const float* bself = (const float*)d_in[7];
    float* out = (float*)d_out;

    detect_kernel<<<1, 256>>>((const unsigned int*)ei);

    const long long zero_items = (long long)N_NODES * D / 4;   // 3.2M
    zero_kernel<<<(int)((zero_items + 255) / 256), 256>>>();

    const long long scat_items = (long long)N_EDGES * (D / 4); // 51.2M
    scatter_kernel<<<(int)((scat_items + 255) / 256), 256>>>(ei, x);

    dim3 grid((N_NODES + 127) / 128, D / 128);                 // 391 x 2
    gemm_kernel<<<grid, 256>>>(x, Wsrc, bsrc, Wdst, bdst, Wself, bself, out);
}